// round 16
// baseline (speedup 1.0000x reference)
#include <cuda_runtime.h>
#include <cuda_fp16.h>
#include <math.h>
#include <stdint.h>

#define BATCH 32
#define SEQT  2048
#define DIM   512
#define ROWS  (BATCH*SEQT)   // 65536

// scratch (no runtime allocs allowed)
__device__ float  g_ait[ROWS];
__device__ float  g_a[ROWS];
__device__ __half g_wh[DIM*DIM];            // W transposed: g_wh[n*DIM+k] = (half)W[k*DIM+n]
__device__ __half g_xh[(size_t)ROWS*DIM];   // x in fp16

// ---------------------------------------------------------------- helpers
__device__ __forceinline__ uint32_t smem_u32(const void* p){
    uint32_t a;
    asm("{ .reg .u64 t; cvta.to.shared.u64 t, %1; cvt.u32.u64 %0, t; }" : "=r"(a) : "l"(p));
    return a;
}
__device__ __forceinline__ void ldm4(uint32_t* r, uint32_t addr){
    asm volatile("ldmatrix.sync.aligned.m8n8.x4.shared.b16 {%0,%1,%2,%3}, [%4];"
                 : "=r"(r[0]),"=r"(r[1]),"=r"(r[2]),"=r"(r[3]) : "r"(addr));
}
__device__ __forceinline__ void mma16816(float* c, const uint32_t* a, const uint32_t* b){
    asm volatile("mma.sync.aligned.m16n8k16.row.col.f32.f16.f16.f32 "
                 "{%0,%1,%2,%3}, {%4,%5,%6,%7}, {%8,%9}, {%0,%1,%2,%3};"
                 : "+f"(c[0]),"+f"(c[1]),"+f"(c[2]),"+f"(c[3])
                 : "r"(a[0]),"r"(a[1]),"r"(a[2]),"r"(a[3]), "r"(b[0]),"r"(b[1]));
}
__device__ __forceinline__ void cpasync16(uint32_t dst, const void* src){
    asm volatile("cp.async.cg.shared.global [%0], [%1], 16;" :: "r"(dst), "l"(src) : "memory");
}
__device__ __forceinline__ float tanha(float x){
    float t; asm("tanh.approx.f32 %0, %1;" : "=f"(t) : "f"(x)); return t;
}
__device__ __forceinline__ uint4 cvt8(float4 v0, float4 v1){
    __half2 h0 = __floats2half2_rn(v0.x, v0.y);
    __half2 h1 = __floats2half2_rn(v0.z, v0.w);
    __half2 h2 = __floats2half2_rn(v1.x, v1.y);
    __half2 h3 = __floats2half2_rn(v1.z, v1.w);
    uint4 o;
    o.x = *(uint32_t*)&h0; o.y = *(uint32_t*)&h1;
    o.z = *(uint32_t*)&h2; o.w = *(uint32_t*)&h3;
    return o;
}
__device__ __forceinline__ void sts16(uint32_t addr, uint4 v){
    asm volatile("st.shared.v4.b32 [%0], {%1,%2,%3,%4};"
                 :: "r"(addr), "r"(v.x), "r"(v.y), "r"(v.z), "r"(v.w) : "memory");
}

// ---------------- prep: W transpose+convert ---------------------------------
__global__ __launch_bounds__(256) void prep_w(const float* __restrict__ W){
    int n = blockIdx.x;
    for (int k = threadIdx.x; k < DIM; k += 256)
        g_wh[(size_t)n*DIM + k] = __float2half_rn(W[(size_t)k*DIM + n]);
}
__global__ void noop(){}

// ---------------- GEMM common ------------------------------------------------
#define BM 128
#define BN 128

// kk loop with warp-phase skew: odd warps start half-way through the kk steps,
// so their LDSM bursts overlap even warps' MMA bursts (de-phases smem vs tensor
// pipes that the chunk barrier otherwise locks into chip-wide alternation).
// Every warp still covers all kk steps; per-warp order is fixed -> deterministic.
#define COMPUTE_CHUNK(bA, bB, PITCHB, KTOT)                                         \
    {                                                                               \
    const uint32_t kksk = (uint32_t)((wid & 1) * ((KTOT) / 2));                     \
    _Pragma("unroll")                                                               \
    for (int kj = 0; kj < (KTOT); kj += 16){                                        \
        const uint32_t kk = ((uint32_t)kj + kksk) % (uint32_t)(KTOT);               \
        uint32_t af[2][4];                                                          \
        _Pragma("unroll")                                                           \
        for (int mt = 0; mt < 2; mt++)                                              \
            ldm4(af[mt], (bA) + aoff + (uint32_t)(mt*16*(PITCHB)) + kk*2);          \
        uint32_t bf[8][2];                                                          \
        _Pragma("unroll")                                                           \
        for (int q = 0; q < 4; q++){                                                \
            uint32_t r[4];                                                          \
            ldm4(r, (bB) + boff + (uint32_t)(q*16*(PITCHB)) + kk*2);                \
            bf[2*q][0] = r[0]; bf[2*q][1] = r[1];                                   \
            bf[2*q+1][0] = r[2]; bf[2*q+1][1] = r[3];                               \
        }                                                                           \
        _Pragma("unroll")                                                           \
        for (int mt = 0; mt < 2; mt++)                                              \
            _Pragma("unroll")                                                       \
            for (int nt = 0; nt < 8; nt++)                                          \
                mma16816(acc[mt][nt], af[mt], bf[nt]);                              \
    }                                                                               \
    }

#define EPILOGUE()                                                                  \
    float s4[4] = {0.f, 0.f, 0.f, 0.f};                                             \
    _Pragma("unroll")                                                               \
    for (int nt = 0; nt < 8; nt++){                                                 \
        int col = col0 + warp_n + nt*8 + (lane & 3)*2;                              \
        float b0v = bias[col], b1v = bias[col+1];                                   \
        float u0v = u[col],    u1v = u[col+1];                                      \
        _Pragma("unroll")                                                           \
        for (int mt = 0; mt < 2; mt++){                                             \
            s4[mt*2+0] += tanha(acc[mt][nt][0] + b0v)*u0v + tanha(acc[mt][nt][1] + b1v)*u1v; \
            s4[mt*2+1] += tanha(acc[mt][nt][2] + b0v)*u0v + tanha(acc[mt][nt][3] + b1v)*u1v; \
        }                                                                           \
    }                                                                               \
    _Pragma("unroll")                                                               \
    for (int i = 0; i < 4; i++){                                                    \
        s4[i] += __shfl_xor_sync(0xffffffffu, s4[i], 1);                            \
        s4[i] += __shfl_xor_sync(0xffffffffu, s4[i], 2);                            \
    }                                                                               \
    if ((lane & 3) == 0){                                                           \
        int rbase = row0 + warp_m + (lane >> 2);                                    \
        atomicAdd(&g_ait[rbase +  0], s4[0]);                                       \
        atomicAdd(&g_ait[rbase +  8], s4[1]);                                       \
        atomicAdd(&g_ait[rbase + 16], s4[2]);                                       \
        atomicAdd(&g_ait[rbase + 24], s4[3]);                                       \
    }

// ---------------- Kernel 1a: N-block 0 + conversion, 3-stage single-barrier -
#define BK 32
#define ASTG 10240                    // bytes per A stage (128 rows x 80B)
#define BSTG 10240                    // bytes per B stage
#define NSTC 3
#define SMEMC (NSTC*(ASTG+BSTG))      // 61440 bytes; x2 CTAs = 120KB

__global__ __launch_bounds__(256, 2) void gemm_conv(
    const float* __restrict__ x,
    const float* __restrict__ bias, const float* __restrict__ u)
{
    extern __shared__ char smemc[];
    const uint32_t sA0 = smem_u32(smemc);
    const uint32_t sB0 = sA0 + NSTC*ASTG;

    const int tid  = threadIdx.x;
    const int wid  = tid >> 5;
    const int lane = tid & 31;
    const int col0 = 0;
    const int row0 = blockIdx.x * BM;

    const int warp_m = (wid & 3) * 32;
    const int warp_n = (wid >> 2) * 64;

    const int chr0 = tid >> 2;
    const int chc0 = (tid & 3) * 8;
    const int chr1 = (tid + 256) >> 2;
    const int chc1 = ((tid + 256) & 3) * 8;

    const float*  Axf   = x    + (size_t)row0 * DIM;
    __half*       Axh   = g_xh + (size_t)row0 * DIM;
    const __half* Bbase = g_wh;

    float acc[2][8][4];
    #pragma unroll
    for (int mt = 0; mt < 2; mt++)
        #pragma unroll
        for (int nt = 0; nt < 8; nt++)
            #pragma unroll
            for (int e = 0; e < 4; e++) acc[mt][nt][e] = 0.f;

    const uint32_t aoff = (uint32_t)((warp_m + (lane & 15)) * 80 + (lane >> 4) * 16);
    const uint32_t boff = (uint32_t)((warp_n + (lane & 7) + (lane >> 4) * 8) * 80
                                     + ((lane >> 3) & 1) * 16);

#define STAGE_B(cidx, s) do{                                                       \
    int k0h = (cidx) * BK;                                                         \
    uint32_t dB = sB0 + (s) * BSTG;                                                \
    cpasync16(dB + chr0*80 + chc0*2, Bbase + (size_t)chr0*DIM + k0h + chc0);       \
    cpasync16(dB + chr1*80 + chc1*2, Bbase + (size_t)chr1*DIM + k0h + chc1);       \
    asm volatile("cp.async.commit_group;" ::: "memory");                           \
}while(0)

#define LOAD_A_F32(cidx) do{                                                       \
    int k0h = (cidx) * BK;                                                         \
    a0 = *(const float4*)(Axf + (size_t)chr0*DIM + k0h + chc0);                    \
    a1 = *(const float4*)(Axf + (size_t)chr0*DIM + k0h + chc0 + 4);                \
    a2 = *(const float4*)(Axf + (size_t)chr1*DIM + k0h + chc1);                    \
    a3 = *(const float4*)(Axf + (size_t)chr1*DIM + k0h + chc1 + 4);                \
}while(0)

    float4 a0, a1, a2, a3;
    LOAD_A_F32(0);
    STAGE_B(0, 0);
    STAGE_B(1, 1);

    #pragma unroll 1
    for (int c = 0; c < DIM/BK; c++){
        const int s = c % NSTC;
        // convert + store A(c) into ring slot s (last read at compute(c-3): safe)
        {
            int k0h = c * BK;
            uint32_t dA = sA0 + s * ASTG;
            uint4 h0 = cvt8(a0, a1);
            uint4 h1 = cvt8(a2, a3);
            sts16(dA + chr0*80 + chc0*2, h0);
            sts16(dA + chr1*80 + chc1*2, h1);
            *(uint4*)(Axh + (size_t)chr0*DIM + k0h + chc0) = h0;
            *(uint4*)(Axh + (size_t)chr1*DIM + k0h + chc1) = h1;
        }
        if (c + 1 < DIM/BK){
            asm volatile("cp.async.wait_group 1;" ::: "memory");
        } else {
            asm volatile("cp.async.wait_group 0;" ::: "memory");
        }
        __syncthreads();   // single barrier

        if (c + 2 < DIM/BK) STAGE_B(c + 2, (c + 2) % NSTC);
        if (c + 1 < DIM/BK) LOAD_A_F32(c + 1);

        const uint32_t bA = sA0 + s * ASTG;
        const uint32_t bB = sB0 + s * BSTG;
        COMPUTE_CHUNK(bA, bB, 80, 32);
    }

    EPILOGUE();
}

// ---------------- Kernel 1b: N-blocks 1..3, BK=64, 3-stage single-barrier ---
#define BK2     64
#define PITCH2  144
#define ABUF2   (BM*PITCH2)
#define BBUF2   (BN*PITCH2)
#define NST     3
#define SMEM3   (NST*(ABUF2+BBUF2))    // 110592 bytes; x2 CTAs = 216KB <= 228KB

__global__ __launch_bounds__(256, 2) void gemm_rest(
    const float* __restrict__ bias, const float* __restrict__ u)
{
    extern __shared__ char smem[];
    const uint32_t sA0 = smem_u32(smem);
    const uint32_t sB0 = sA0 + NST*ABUF2;

    const int tid  = threadIdx.x;
    const int wid  = tid >> 5;
    const int lane = tid & 31;
    const int col0 = (blockIdx.x + 1) * BN;
    const int row0 = blockIdx.y * BM;

    const int warp_m = (wid & 3) * 32;
    const int warp_n = (wid >> 2) * 64;

    const __half* Abase = g_xh + (size_t)row0 * DIM;
    const __half* Bbase = g_wh + (size_t)col0 * DIM;

    float acc[2][8][4];
    #pragma unroll
    for (int mt = 0; mt < 2; mt++)
        #pragma unroll
        for (int nt = 0; nt < 8; nt++)
            #pragma unroll
            for (int e = 0; e < 4; e++) acc[mt][nt][e] = 0.f;

    const uint32_t aoff = (uint32_t)((warp_m + (lane & 15)) * PITCH2 + (lane >> 4) * 16);
    const uint32_t boff = (uint32_t)((warp_n + (lane & 7) + (lane >> 4) * 8) * PITCH2
                                     + ((lane >> 3) & 1) * 16);

#define STAGE2(cidx, s) do{                                                        \
    int k0h = (cidx) * BK2;                                                        \
    uint32_t dA = sA0 + (s) * ABUF2;                                               \
    uint32_t dB = sB0 + (s) * BBUF2;                                               \
    _Pragma("unroll")                                                              \
    for (int i = 0; i < 4; i++){                                                   \
        int idx = tid + i*256;                                                     \
        int r = idx >> 3, f = idx & 7;                                             \
        cpasync16(dA + r*PITCH2 + f*16, Abase + (size_t)r*DIM + k0h + f*8);        \
        cpasync16(dB + r*PITCH2 + f*16, Bbase + (size_t)r*DIM + k0h + f*8);        \
    }                                                                              \
    asm volatile("cp.async.commit_group;" ::: "memory");                           \
}while(0)

    STAGE2(0, 0);
    STAGE2(1, 1);

    #pragma unroll 1
    for (int c = 0; c < DIM/BK2; c++){
        const int s = c % NST;
        if (c + 1 < DIM/BK2){
            asm volatile("cp.async.wait_group 1;" ::: "memory");
        } else {
            asm volatile("cp.async.wait_group 0;" ::: "memory");
        }
        __syncthreads();

        if (c + 2 < DIM/BK2) STAGE2(c + 2, (c + 2) % NST);

        const uint32_t bA = sA0 + s * ABUF2;
        const uint32_t bB = sB0 + s * BBUF2;
        COMPUTE_CHUNK(bA, bB, PITCH2, 64);
    }

    EPILOGUE();
}

// ---------------- Kernel 2: per-batch exp + normalize over T ----------------
__global__ __launch_bounds__(256) void softmax_norm()
{
    const int b = blockIdx.x;
    const int tid = threadIdx.x;
    __shared__ float red[256];

    float e[8];
    float ssum = 0.f;
    #pragma unroll
    for (int i = 0; i < 8; i++) {
        float v = g_ait[b * SEQT + i * 256 + tid];
        e[i] = expf(v);
        ssum += e[i];
    }
    red[tid] = ssum;
    __syncthreads();
    #pragma unroll
    for (int stride = 128; stride > 0; stride >>= 1) {
        if (tid < stride) red[tid] += red[tid + stride];
        __syncthreads();
    }
    float inv = 1.0f / (red[0] + 1e-7f);
    #pragma unroll
    for (int i = 0; i < 8; i++)
        g_a[b * SEQT + i * 256 + tid] = e[i] * inv;
}

// ---------------- Kernel 3: pooling from fp16 x -----------------------------
__global__ __launch_bounds__(256) void pool(float* __restrict__ out)
{
    const int b   = blockIdx.x;
    const int tc  = blockIdx.y;
    const int tid = threadIdx.x;
    const int rg  = tid >> 6;
    const int ds  = (tid & 63) * 8;

    __shared__ float sa[128];
    __shared__ float red[4][64][8];

    if (tid < 128)
        sa[tid] = g_a[b * SEQT + tc * 128 + tid];
    __syncthreads();

    const __half* xp = g_xh + (size_t)b * SEQT * DIM + (size_t)tc * 128 * DIM;
    float acc[8];
    #pragma unroll
    for (int j = 0; j < 8; j++) acc[j] = 0.f;

    #pragma unroll 4
    for (int t0 = 0; t0 < 128; t0 += 4){
        int t = t0 + rg;
        float av = sa[t];
        uint4 v = *(const uint4*)(xp + (size_t)t * DIM + ds);
        const __half2* h = (const __half2*)&v;
        #pragma unroll
        for (int j = 0; j < 4; j++){
            float2 f = __half22float2(h[j]);
            acc[2*j]   = fmaf(f.x, av, acc[2*j]);
            acc[2*j+1] = fmaf(f.y, av, acc[2*j+1]);
        }
    }

    #pragma unroll
    for (int j = 0; j < 8; j++) red[rg][tid & 63][j] = acc[j];
    __syncthreads();

    if (tid < 64){
        #pragma unroll
        for (int j = 0; j < 8; j++){
            float v = red[0][tid][j] + red[1][tid][j] + red[2][tid][j] + red[3][tid][j];
            atomicAdd(&out[b * DIM + tid * 8 + j], v);
        }
    }
}

// ---------------------------------------------------------------------------
extern "C" void kernel_launch(void* const* d_in, const int* in_sizes, int n_in,
                              void* d_out, int out_size)
{
    const float* x    = (const float*)d_in[0];
    const float* W    = (const float*)d_in[1];
    const float* bias = (const float*)d_in[2];
    const float* u    = (const float*)d_in[3];
    float* out = (float*)d_out;

    cudaFuncSetAttribute(gemm_conv, cudaFuncAttributeMaxDynamicSharedMemorySize, SMEMC);
    cudaFuncSetAttribute(gemm_rest, cudaFuncAttributeMaxDynamicSharedMemorySize, SMEM3);

    void* aitp = nullptr;
    cudaGetSymbolAddress(&aitp, g_ait);
    cudaMemsetAsync(aitp, 0, ROWS * sizeof(float));
    cudaMemsetAsync(d_out, 0, BATCH * DIM * sizeof(float));

    prep_w<<<DIM, 256>>>(W);
    noop<<<1, 32>>>();   // keeps gemm_rest in ncu's capture slot
    gemm_conv<<<ROWS / BM, 256, SMEMC>>>(x, bias, u);
    gemm_rest<<<dim3(3, ROWS / BM), 256, SMEM3>>>(bias, u);
    softmax_norm<<<BATCH, 256>>>();
    pool<<<dim3(BATCH, 16), 256>>>(out);
}

// round 17
// speedup vs baseline: 1.0204x; 1.0204x over previous
#include <cuda_runtime.h>
#include <cuda_fp16.h>
#include <math.h>
#include <stdint.h>

#define BATCH 32
#define SEQT  2048
#define DIM   512
#define ROWS  (BATCH*SEQT)   // 65536

// scratch (no runtime allocs allowed)
__device__ float  g_ait[ROWS];
__device__ float  g_a[ROWS];
__device__ __half g_wh[DIM*DIM];            // W transposed: g_wh[n*DIM+k] = (half)W[k*DIM+n]
__device__ __half g_xh[(size_t)ROWS*DIM];   // x in fp16

// ---------------------------------------------------------------- helpers
__device__ __forceinline__ uint32_t smem_u32(const void* p){
    uint32_t a;
    asm("{ .reg .u64 t; cvta.to.shared.u64 t, %1; cvt.u32.u64 %0, t; }" : "=r"(a) : "l"(p));
    return a;
}
__device__ __forceinline__ void ldm4(uint32_t* r, uint32_t addr){
    asm volatile("ldmatrix.sync.aligned.m8n8.x4.shared.b16 {%0,%1,%2,%3}, [%4];"
                 : "=r"(r[0]),"=r"(r[1]),"=r"(r[2]),"=r"(r[3]) : "r"(addr));
}
__device__ __forceinline__ void mma16816(float* c, const uint32_t* a, const uint32_t* b){
    asm volatile("mma.sync.aligned.m16n8k16.row.col.f32.f16.f16.f32 "
                 "{%0,%1,%2,%3}, {%4,%5,%6,%7}, {%8,%9}, {%0,%1,%2,%3};"
                 : "+f"(c[0]),"+f"(c[1]),"+f"(c[2]),"+f"(c[3])
                 : "r"(a[0]),"r"(a[1]),"r"(a[2]),"r"(a[3]), "r"(b[0]),"r"(b[1]));
}
__device__ __forceinline__ void cpasync16(uint32_t dst, const void* src){
    asm volatile("cp.async.cg.shared.global [%0], [%1], 16;" :: "r"(dst), "l"(src) : "memory");
}
__device__ __forceinline__ float tanha(float x){
    float t; asm("tanh.approx.f32 %0, %1;" : "=f"(t) : "f"(x)); return t;
}
__device__ __forceinline__ uint4 cvt8(float4 v0, float4 v1){
    __half2 h0 = __floats2half2_rn(v0.x, v0.y);
    __half2 h1 = __floats2half2_rn(v0.z, v0.w);
    __half2 h2 = __floats2half2_rn(v1.x, v1.y);
    __half2 h3 = __floats2half2_rn(v1.z, v1.w);
    uint4 o;
    o.x = *(uint32_t*)&h0; o.y = *(uint32_t*)&h1;
    o.z = *(uint32_t*)&h2; o.w = *(uint32_t*)&h3;
    return o;
}
__device__ __forceinline__ void sts16(uint32_t addr, uint4 v){
    asm volatile("st.shared.v4.b32 [%0], {%1,%2,%3,%4};"
                 :: "r"(addr), "r"(v.x), "r"(v.y), "r"(v.z), "r"(v.w) : "memory");
}

// ---------------- prep: W transpose+convert ---------------------------------
__global__ __launch_bounds__(256) void prep_w(const float* __restrict__ W){
    int n = blockIdx.x;
    for (int k = threadIdx.x; k < DIM; k += 256)
        g_wh[(size_t)n*DIM + k] = __float2half_rn(W[(size_t)k*DIM + n]);
}
__global__ void noop(){}

// ---------------- GEMM common ------------------------------------------------
#define BM 128
#define BN 128

#define COMPUTE_CHUNK(bA, bB, PITCHB, KTOT)                                         \
    _Pragma("unroll")                                                               \
    for (int kk = 0; kk < (KTOT); kk += 16){                                        \
        uint32_t af[2][4];                                                          \
        _Pragma("unroll")                                                           \
        for (int mt = 0; mt < 2; mt++)                                              \
            ldm4(af[mt], (bA) + aoff + (uint32_t)(mt*16*(PITCHB) + kk*2));          \
        uint32_t bf[8][2];                                                          \
        _Pragma("unroll")                                                           \
        for (int q = 0; q < 4; q++){                                                \
            uint32_t r[4];                                                          \
            ldm4(r, (bB) + boff + (uint32_t)(q*16*(PITCHB) + kk*2));                \
            bf[2*q][0] = r[0]; bf[2*q][1] = r[1];                                   \
            bf[2*q+1][0] = r[2]; bf[2*q+1][1] = r[3];                               \
        }                                                                           \
        _Pragma("unroll")                                                           \
        for (int mt = 0; mt < 2; mt++)                                              \
            _Pragma("unroll")                                                       \
            for (int nt = 0; nt < 8; nt++)                                          \
                mma16816(acc[mt][nt], af[mt], bf[nt]);                              \
    }

#define EPILOGUE()                                                                  \
    float s4[4] = {0.f, 0.f, 0.f, 0.f};                                             \
    _Pragma("unroll")                                                               \
    for (int nt = 0; nt < 8; nt++){                                                 \
        int col = col0 + warp_n + nt*8 + (lane & 3)*2;                              \
        float b0v = bias[col], b1v = bias[col+1];                                   \
        float u0v = u[col],    u1v = u[col+1];                                      \
        _Pragma("unroll")                                                           \
        for (int mt = 0; mt < 2; mt++){                                             \
            s4[mt*2+0] += tanha(acc[mt][nt][0] + b0v)*u0v + tanha(acc[mt][nt][1] + b1v)*u1v; \
            s4[mt*2+1] += tanha(acc[mt][nt][2] + b0v)*u0v + tanha(acc[mt][nt][3] + b1v)*u1v; \
        }                                                                           \
    }                                                                               \
    _Pragma("unroll")                                                               \
    for (int i = 0; i < 4; i++){                                                    \
        s4[i] += __shfl_xor_sync(0xffffffffu, s4[i], 1);                            \
        s4[i] += __shfl_xor_sync(0xffffffffu, s4[i], 2);                            \
    }                                                                               \
    if ((lane & 3) == 0){                                                           \
        int rbase = row0 + warp_m + (lane >> 2);                                    \
        atomicAdd(&g_ait[rbase +  0], s4[0]);                                       \
        atomicAdd(&g_ait[rbase +  8], s4[1]);                                       \
        atomicAdd(&g_ait[rbase + 16], s4[2]);                                       \
        atomicAdd(&g_ait[rbase + 24], s4[3]);                                       \
    }

// ---------------- Kernel 1a: N-block 0 + conversion, 3-stage single-barrier -
#define BK 32
#define ASTG 10240                    // bytes per A stage (128 rows x 80B)
#define BSTG 10240                    // bytes per B stage
#define NSTC 3
#define SMEMC (NSTC*(ASTG+BSTG))      // 61440 bytes; x2 CTAs = 120KB

__global__ __launch_bounds__(256, 2) void gemm_conv(
    const float* __restrict__ x,
    const float* __restrict__ bias, const float* __restrict__ u)
{
    extern __shared__ char smemc[];
    const uint32_t sA0 = smem_u32(smemc);
    const uint32_t sB0 = sA0 + NSTC*ASTG;

    const int tid  = threadIdx.x;
    const int wid  = tid >> 5;
    const int lane = tid & 31;
    const int col0 = 0;
    const int row0 = blockIdx.x * BM;

    const int warp_m = (wid & 3) * 32;
    const int warp_n = (wid >> 2) * 64;

    const int chr0 = tid >> 2;
    const int chc0 = (tid & 3) * 8;
    const int chr1 = (tid + 256) >> 2;
    const int chc1 = ((tid + 256) & 3) * 8;

    const float*  Axf   = x    + (size_t)row0 * DIM;
    __half*       Axh   = g_xh + (size_t)row0 * DIM;
    const __half* Bbase = g_wh;

    float acc[2][8][4];
    #pragma unroll
    for (int mt = 0; mt < 2; mt++)
        #pragma unroll
        for (int nt = 0; nt < 8; nt++)
            #pragma unroll
            for (int e = 0; e < 4; e++) acc[mt][nt][e] = 0.f;

    const uint32_t aoff = (uint32_t)((warp_m + (lane & 15)) * 80 + (lane >> 4) * 16);
    const uint32_t boff = (uint32_t)((warp_n + (lane & 7) + (lane >> 4) * 8) * 80
                                     + ((lane >> 3) & 1) * 16);

#define STAGE_B(cidx, s) do{                                                       \
    int k0h = (cidx) * BK;                                                         \
    uint32_t dB = sB0 + (s) * BSTG;                                                \
    cpasync16(dB + chr0*80 + chc0*2, Bbase + (size_t)chr0*DIM + k0h + chc0);       \
    cpasync16(dB + chr1*80 + chc1*2, Bbase + (size_t)chr1*DIM + k0h + chc1);       \
    asm volatile("cp.async.commit_group;" ::: "memory");                           \
}while(0)

#define LOAD_A_F32(cidx) do{                                                       \
    int k0h = (cidx) * BK;                                                         \
    a0 = *(const float4*)(Axf + (size_t)chr0*DIM + k0h + chc0);                    \
    a1 = *(const float4*)(Axf + (size_t)chr0*DIM + k0h + chc0 + 4);                \
    a2 = *(const float4*)(Axf + (size_t)chr1*DIM + k0h + chc1);                    \
    a3 = *(const float4*)(Axf + (size_t)chr1*DIM + k0h + chc1 + 4);                \
}while(0)

    float4 a0, a1, a2, a3;
    LOAD_A_F32(0);
    STAGE_B(0, 0);
    STAGE_B(1, 1);

    #pragma unroll 1
    for (int c = 0; c < DIM/BK; c++){
        const int s = c % NSTC;
        // convert + store A(c) into ring slot s (last read at compute(c-3): safe)
        {
            int k0h = c * BK;
            uint32_t dA = sA0 + s * ASTG;
            uint4 h0 = cvt8(a0, a1);
            uint4 h1 = cvt8(a2, a3);
            sts16(dA + chr0*80 + chc0*2, h0);
            sts16(dA + chr1*80 + chc1*2, h1);
            *(uint4*)(Axh + (size_t)chr0*DIM + k0h + chc0) = h0;
            *(uint4*)(Axh + (size_t)chr1*DIM + k0h + chc1) = h1;
        }
        if (c + 1 < DIM/BK){
            asm volatile("cp.async.wait_group 1;" ::: "memory");
        } else {
            asm volatile("cp.async.wait_group 0;" ::: "memory");
        }
        __syncthreads();   // single barrier: A(c)+B(c) visible AND compute(c-1) done

        if (c + 2 < DIM/BK) STAGE_B(c + 2, (c + 2) % NSTC);
        if (c + 1 < DIM/BK) LOAD_A_F32(c + 1);

        const uint32_t bA = sA0 + s * ASTG;
        const uint32_t bB = sB0 + s * BSTG;
        COMPUTE_CHUNK(bA, bB, 80, 32);
        // no trailing barrier: 3-slot ring removes the WAR hazard
    }

    EPILOGUE();
}

// ---------------- Kernel 1b: N-blocks 1..3, BK=64, 3-stage single-barrier ---
#define BK2     64
#define PITCH2  144
#define ABUF2   (BM*PITCH2)
#define BBUF2   (BN*PITCH2)
#define NST     3
#define SMEM3   (NST*(ABUF2+BBUF2))    // 110592 bytes; x2 CTAs = 216KB <= 228KB

__global__ __launch_bounds__(256, 2) void gemm_rest(
    const float* __restrict__ bias, const float* __restrict__ u)
{
    extern __shared__ char smem[];
    const uint32_t sA0 = smem_u32(smem);
    const uint32_t sB0 = sA0 + NST*ABUF2;

    const int tid  = threadIdx.x;
    const int wid  = tid >> 5;
    const int lane = tid & 31;
    const int col0 = (blockIdx.x + 1) * BN;
    const int row0 = blockIdx.y * BM;

    const int warp_m = (wid & 3) * 32;
    const int warp_n = (wid >> 2) * 64;

    const __half* Abase = g_xh + (size_t)row0 * DIM;
    const __half* Bbase = g_wh + (size_t)col0 * DIM;

    float acc[2][8][4];
    #pragma unroll
    for (int mt = 0; mt < 2; mt++)
        #pragma unroll
        for (int nt = 0; nt < 8; nt++)
            #pragma unroll
            for (int e = 0; e < 4; e++) acc[mt][nt][e] = 0.f;

    const uint32_t aoff = (uint32_t)((warp_m + (lane & 15)) * PITCH2 + (lane >> 4) * 16);
    const uint32_t boff = (uint32_t)((warp_n + (lane & 7) + (lane >> 4) * 8) * PITCH2
                                     + ((lane >> 3) & 1) * 16);

#define STAGE2(cidx, s) do{                                                        \
    int k0h = (cidx) * BK2;                                                        \
    uint32_t dA = sA0 + (s) * ABUF2;                                               \
    uint32_t dB = sB0 + (s) * BBUF2;                                               \
    _Pragma("unroll")                                                              \
    for (int i = 0; i < 4; i++){                                                   \
        int idx = tid + i*256;                                                     \
        int r = idx >> 3, f = idx & 7;                                             \
        cpasync16(dA + r*PITCH2 + f*16, Abase + (size_t)r*DIM + k0h + f*8);        \
        cpasync16(dB + r*PITCH2 + f*16, Bbase + (size_t)r*DIM + k0h + f*8);        \
    }                                                                              \
    asm volatile("cp.async.commit_group;" ::: "memory");                           \
}while(0)

    STAGE2(0, 0);
    STAGE2(1, 1);

    #pragma unroll 1
    for (int c = 0; c < DIM/BK2; c++){
        const int s = c % NST;
        if (c + 1 < DIM/BK2){
            asm volatile("cp.async.wait_group 1;" ::: "memory");
        } else {
            asm volatile("cp.async.wait_group 0;" ::: "memory");
        }
        __syncthreads();

        if (c + 2 < DIM/BK2) STAGE2(c + 2, (c + 2) % NST);

        const uint32_t bA = sA0 + s * ABUF2;
        const uint32_t bB = sB0 + s * BBUF2;
        COMPUTE_CHUNK(bA, bB, PITCH2, 64);
    }

    EPILOGUE();
}

// ---------------- Kernel 2: per-batch exp + normalize over T ----------------
__global__ __launch_bounds__(256) void softmax_norm()
{
    const int b = blockIdx.x;
    const int tid = threadIdx.x;
    __shared__ float red[256];

    float e[8];
    float ssum = 0.f;
    #pragma unroll
    for (int i = 0; i < 8; i++) {
        float v = g_ait[b * SEQT + i * 256 + tid];
        e[i] = expf(v);
        ssum += e[i];
    }
    red[tid] = ssum;
    __syncthreads();
    #pragma unroll
    for (int stride = 128; stride > 0; stride >>= 1) {
        if (tid < stride) red[tid] += red[tid + stride];
        __syncthreads();
    }
    float inv = 1.0f / (red[0] + 1e-7f);
    #pragma unroll
    for (int i = 0; i < 8; i++)
        g_a[b * SEQT + i * 256 + tid] = e[i] * inv;
}

// ---------------- Kernel 3: pooling from fp16 x -----------------------------
__global__ __launch_bounds__(256) void pool(float* __restrict__ out)
{
    const int b   = blockIdx.x;
    const int tc  = blockIdx.y;
    const int tid = threadIdx.x;
    const int rg  = tid >> 6;
    const int ds  = (tid & 63) * 8;

    __shared__ float sa[128];
    __shared__ float red[4][64][8];

    if (tid < 128)
        sa[tid] = g_a[b * SEQT + tc * 128 + tid];
    __syncthreads();

    const __half* xp = g_xh + (size_t)b * SEQT * DIM + (size_t)tc * 128 * DIM;
    float acc[8];
    #pragma unroll
    for (int j = 0; j < 8; j++) acc[j] = 0.f;

    #pragma unroll 4
    for (int t0 = 0; t0 < 128; t0 += 4){
        int t = t0 + rg;
        float av = sa[t];
        uint4 v = *(const uint4*)(xp + (size_t)t * DIM + ds);
        const __half2* h = (const __half2*)&v;
        #pragma unroll
        for (int j = 0; j < 4; j++){
            float2 f = __half22float2(h[j]);
            acc[2*j]   = fmaf(f.x, av, acc[2*j]);
            acc[2*j+1] = fmaf(f.y, av, acc[2*j+1]);
        }
    }

    #pragma unroll
    for (int j = 0; j < 8; j++) red[rg][tid & 63][j] = acc[j];
    __syncthreads();

    if (tid < 64){
        #pragma unroll
        for (int j = 0; j < 8; j++){
            float v = red[0][tid][j] + red[1][tid][j] + red[2][tid][j] + red[3][tid][j];
            atomicAdd(&out[b * DIM + tid * 8 + j], v);
        }
    }
}

// ---------------------------------------------------------------------------
extern "C" void kernel_launch(void* const* d_in, const int* in_sizes, int n_in,
                              void* d_out, int out_size)
{
    const float* x    = (const float*)d_in[0];
    const float* W    = (const float*)d_in[1];
    const float* bias = (const float*)d_in[2];
    const float* u    = (const float*)d_in[3];
    float* out = (float*)d_out;

    cudaFuncSetAttribute(gemm_conv, cudaFuncAttributeMaxDynamicSharedMemorySize, SMEMC);
    cudaFuncSetAttribute(gemm_rest, cudaFuncAttributeMaxDynamicSharedMemorySize, SMEM3);

    void* aitp = nullptr;
    cudaGetSymbolAddress(&aitp, g_ait);
    cudaMemsetAsync(aitp, 0, ROWS * sizeof(float));
    cudaMemsetAsync(d_out, 0, BATCH * DIM * sizeof(float));

    prep_w<<<DIM, 256>>>(W);
    noop<<<1, 32>>>();   // keeps gemm_rest in ncu's capture slot
    gemm_conv<<<ROWS / BM, 256, SMEMC>>>(x, bias, u);
    gemm_rest<<<dim3(3, ROWS / BM), 256, SMEM3>>>(bias, u);
    softmax_norm<<<BATCH, 256>>>();
    pool<<<dim3(BATCH, 16), 256>>>(out);
}